// round 6
// baseline (speedup 1.0000x reference)
#include <cuda_runtime.h>
#include <cstdint>

#define DD      512
#define HK      2048
#define NB      1024
#define LSLOTS  50
#define KSW     8            // split-K for W gemm
#define KST     4            // split-K for temp gemm
#define NBLK    128          // compute blocks participating in grid barrier
#define NPREF   128          // prefetch blocks
#define N4ALL   (LSLOTS * NB * DD / 4)   // 6,553,600 float4

// Scratch (static device globals — no allocation)
__device__ float g_Wpart[KSW * DD * DD];     // split-K partials of Wt[j,a]
__device__ float g_W[DD * DD];               // Wt[j][a] = (wv@wo)[a][j]
__device__ float g_c[DD];                    // bv@wo + bo
__device__ float g_Tpart[KST * NB * DD];     // split-K partials of hid@Wt^T
__device__ float g_temp[NB * DD];            // 3w*(hid@W + c)
__device__ float g_dummy[NPREF * 8];         // prefetch sink (deterministic)

// grid barrier state (generation persists across replays; monotone)
__device__ int g_bar_count = 0;
__device__ volatile int g_bar_gen = 0;

__device__ __forceinline__ void grid_bar() {
    __syncthreads();
    if (threadIdx.x == 0) {
        __threadfence();
        int gen = g_bar_gen;
        if (atomicAdd(&g_bar_count, 1) == NBLK - 1) {
            g_bar_count = 0;
            __threadfence();
            g_bar_gen = gen + 1;
        } else {
            while (g_bar_gen == gen) { }
        }
        __threadfence();
    }
    __syncthreads();
}

// ---------------------------------------------------------------------------
// helpers
// ---------------------------------------------------------------------------
__device__ __forceinline__ uint32_t f2tf(float x) {
    uint32_t r; asm("cvt.rna.tf32.f32 %0, %1;" : "=r"(r) : "f"(x)); return r;
}
__device__ __forceinline__ void mma8(float* d, const uint32_t* a, const uint32_t* b) {
    asm volatile(
        "mma.sync.aligned.m16n8k8.row.col.f32.tf32.tf32.f32 "
        "{%0,%1,%2,%3}, {%4,%5,%6,%7}, {%8,%9}, {%0,%1,%2,%3};"
        : "+f"(d[0]), "+f"(d[1]), "+f"(d[2]), "+f"(d[3])
        : "r"(a[0]), "r"(a[1]), "r"(a[2]), "r"(a[3]), "r"(b[0]), "r"(b[1]));
}

// ---------------------------------------------------------------------------
// TF32 mma.sync GEMM device fn: C[z][m,n] = sum_{k in chunk z} A[m,k]*B[n,k]
//   ATR=false: A row-major [m][LDA] K-contig; ATR=true: A is [k][LDA] m-contig.
// Tile 128x128, Kc=32 per stage, double-buffered smem, 256 threads / 8 warps.
// ---------------------------------------------------------------------------
#define ASZ    4608          // 128*36 words (ATR uses 32*132=4224 of it)
#define BSZ    4608
#define STAGE  (ASZ + BSZ)
#define SMEM_WORDS (2 * STAGE)
#define SMEM_BYTES (SMEM_WORDS * 4)

template<bool ATR, int LDA, int LDB, int MTOT, int NTOT, int KCHUNK>
__device__ __forceinline__ void gemm_dev(const float* __restrict__ Ag,
                                         const float* __restrict__ Bg,
                                         float* __restrict__ C,
                                         uint32_t* smem,
                                         int bx, int by, int bz) {
    const int t = threadIdx.x;
    const int nBase = bx * 128;
    const int mBase = by * 128;
    const int kb    = bz * KCHUNK;

    const bool isA = (t < 128);
    const int tt = t & 127;
    const int rr = tt >> 3;
    const int fc = tt & 7;
    const int jq = tt & 31;
    const int kr = tt >> 5;

    constexpr int NS = KCHUNK / 32;
    float4 rg[8];

#define LDG(s)                                                                  \
    {                                                                           \
        if (isA) {                                                              \
            if (ATR) {                                                          \
                _Pragma("unroll")                                               \
                for (int i = 0; i < 8; ++i)                                     \
                    rg[i] = *(const float4*)&Ag[(size_t)(kb + (s)*32 + kr + 4*i) * LDA \
                                                + mBase + jq * 4];              \
            } else {                                                            \
                _Pragma("unroll")                                               \
                for (int i = 0; i < 8; ++i)                                     \
                    rg[i] = *(const float4*)&Ag[(size_t)(mBase + rr + 16*i) * LDA \
                                                + kb + (s)*32 + fc * 4];        \
            }                                                                   \
        } else {                                                                \
            _Pragma("unroll")                                                   \
            for (int i = 0; i < 8; ++i)                                         \
                rg[i] = *(const float4*)&Bg[(size_t)(nBase + rr + 16*i) * LDB   \
                                            + kb + (s)*32 + fc * 4];            \
        }                                                                       \
    }

    const int w = t >> 5, lane = t & 31;
    const int moff = (w & 3) * 32;
    const int noff = (w >> 2) * 64;
    const int g = lane >> 2, q = lane & 3;

    float acc[2][8][4];
#pragma unroll
    for (int mt = 0; mt < 2; mt++)
#pragma unroll
        for (int nt = 0; nt < 8; nt++)
#pragma unroll
            for (int r = 0; r < 4; r++) acc[mt][nt][r] = 0.0f;

    LDG(0);

    for (int s = 0; s < NS; ++s) {
        const int buf = s & 1;
        uint32_t* dst = smem + buf * STAGE + (isA ? 0 : ASZ);
        if (isA && ATR) {
#pragma unroll
            for (int i = 0; i < 8; ++i) {
                uint32_t* p = dst + (kr + 4 * i) * 132 + jq * 4;
                p[0] = f2tf(rg[i].x); p[1] = f2tf(rg[i].y);
                p[2] = f2tf(rg[i].z); p[3] = f2tf(rg[i].w);
            }
        } else {
#pragma unroll
            for (int i = 0; i < 8; ++i) {
                uint32_t* p = dst + (rr + 16 * i) * 36 + fc * 4;
                p[0] = f2tf(rg[i].x); p[1] = f2tf(rg[i].y);
                p[2] = f2tf(rg[i].z); p[3] = f2tf(rg[i].w);
            }
        }
        __syncthreads();
        if (s + 1 < NS) LDG(s + 1);

        const uint32_t* As = smem + buf * STAGE;
        const uint32_t* Bs = As + ASZ;
#pragma unroll
        for (int k0 = 0; k0 < 32; k0 += 8) {
            uint32_t af[2][4];
#pragma unroll
            for (int mt = 0; mt < 2; mt++) {
                const int m0 = moff + mt * 16 + g;
                if (ATR) {
                    af[mt][0] = As[(k0 + q) * 132 + m0];
                    af[mt][1] = As[(k0 + q) * 132 + m0 + 8];
                    af[mt][2] = As[(k0 + q + 4) * 132 + m0];
                    af[mt][3] = As[(k0 + q + 4) * 132 + m0 + 8];
                } else {
                    af[mt][0] = As[m0 * 36 + k0 + q];
                    af[mt][1] = As[(m0 + 8) * 36 + k0 + q];
                    af[mt][2] = As[m0 * 36 + k0 + q + 4];
                    af[mt][3] = As[(m0 + 8) * 36 + k0 + q + 4];
                }
            }
            uint32_t bf[8][2];
#pragma unroll
            for (int nt = 0; nt < 8; nt++) {
                const int n0 = noff + nt * 8 + g;
                bf[nt][0] = Bs[n0 * 36 + k0 + q];
                bf[nt][1] = Bs[n0 * 36 + k0 + q + 4];
            }
#pragma unroll
            for (int mt = 0; mt < 2; mt++)
#pragma unroll
                for (int nt = 0; nt < 8; nt++)
                    mma8(acc[mt][nt], af[mt], bf[nt]);
        }
        __syncthreads();
    }
#undef LDG

    float* cz = C + (size_t)bz * MTOT * NTOT;
#pragma unroll
    for (int mt = 0; mt < 2; mt++) {
        const int r0 = mBase + moff + mt * 16 + g;
#pragma unroll
        for (int nt = 0; nt < 8; nt++) {
            const int c0 = nBase + noff + nt * 8 + q * 2;
            float2 v0 = make_float2(acc[mt][nt][0], acc[mt][nt][1]);
            float2 v1 = make_float2(acc[mt][nt][2], acc[mt][nt][3]);
            *(float2*)&cz[(size_t)r0 * NTOT + c0] = v0;
            *(float2*)&cz[(size_t)(r0 + 8) * NTOT + c0] = v1;
        }
    }
}

// ---------------------------------------------------------------------------
// Fused persistent kernel.
// Blocks [0,128): P0 gemm_w | P1 reduce_w + bias_c | P2 gemm_temp | P3 reduce.
// Blocks [128,256): prefetch momery into L2 (__ldcg), no barrier participation.
// ---------------------------------------------------------------------------
__global__ __launch_bounds__(256, 2) void k_fused(const float* __restrict__ wo,
                                                  const float* __restrict__ wv,
                                                  const float* __restrict__ hid,
                                                  const float* __restrict__ bv,
                                                  const float* __restrict__ bo,
                                                  const float* __restrict__ wsc,
                                                  const float4* __restrict__ mom) {
    extern __shared__ uint32_t smem[];
    __shared__ float sred[8];
    const int b = blockIdx.x;
    const int t = threadIdx.x;

    if (b >= NBLK) {
        // ---- prefetcher: stream momery into L2
        const int pb = b - NBLK;
        float4 s = make_float4(0.f, 0.f, 0.f, 0.f);
        int i = pb * 256 + t;                 // stride NPREF*256 = 32768
        // 200 iterations, unrolled 4 for MLP
        for (; i + 3 * 32768 < N4ALL; i += 4 * 32768) {
            float4 v0 = __ldcg(&mom[i]);
            float4 v1 = __ldcg(&mom[i + 32768]);
            float4 v2 = __ldcg(&mom[i + 2 * 32768]);
            float4 v3 = __ldcg(&mom[i + 3 * 32768]);
            s.x += v0.x + v1.x + v2.x + v3.x;
            s.y += v0.y + v1.y + v2.y + v3.y;
            s.z += v0.z + v1.z + v2.z + v3.z;
            s.w += v0.w + v1.w + v2.w + v3.w;
        }
        for (; i < N4ALL; i += 32768) {
            float4 v = __ldcg(&mom[i]);
            s.x += v.x; s.y += v.y; s.z += v.z; s.w += v.w;
        }
        float acc = s.x + s.y + s.z + s.w;
#pragma unroll
        for (int off = 16; off > 0; off >>= 1)
            acc += __shfl_down_sync(0xFFFFFFFFu, acc, off);
        if ((t & 31) == 0) g_dummy[pb * 8 + (t >> 5)] = acc;
        return;
    }

    // ---- P0: Wt partials  Wt[j,a] = sum_k wo[k,j] * wv[a,k]
    gemm_dev<true, DD, HK, DD, DD, HK / KSW>(wo, wv, g_Wpart, smem,
                                             b & 3, (b >> 2) & 3, b >> 4);
    grid_bar();

    // ---- P1a: reduce W partials (65536 float4 over 128 blocks => 2/thread)
    {
        const float4* p = (const float4*)g_Wpart;
#pragma unroll
        for (int u = 0; u < 2; ++u) {
            int i = b * 512 + u * 256 + t;
            float4 s = p[i];
#pragma unroll
            for (int k = 1; k < KSW; k++) {
                float4 v = p[k * (DD * DD / 4) + i];
                s.x += v.x; s.y += v.y; s.z += v.z; s.w += v.w;
            }
            ((float4*)g_W)[i] = s;
        }
    }
    // ---- P1b: bias c[j] = sum_k bv[k]*wo[k,j] + bo[j]  (4 j's per block)
    {
        const int j = b * 4 + (t >> 6);
        const int l64 = t & 63;
        float acc = 0.0f;
        const int k0 = l64 * 32;
        for (int k = k0; k < k0 + 32; k++)
            acc += bv[k] * wo[(size_t)k * DD + j];
#pragma unroll
        for (int off = 16; off > 0; off >>= 1)
            acc += __shfl_down_sync(0xFFFFFFFFu, acc, off);
        if ((t & 31) == 0) sred[t >> 5] = acc;
        __syncthreads();
        if (t < 4) g_c[b * 4 + t] = sred[2 * t] + sred[2 * t + 1] + bo[b * 4 + t];
    }
    grid_bar();

    // ---- P2: temp partials  Tpart[z][b,j] = sum_a hid[b,a]*Wt[j,a]
    gemm_dev<false, DD, DD, NB, DD, DD / KST>(hid, g_W, g_Tpart, smem,
                                              b & 3, (b >> 2) & 7, b >> 5);
    grid_bar();

    // ---- P3: temp = 3w * (sum partials + c)   (131072 float4 => 4/thread)
    {
        const float sc = 3.0f * wsc[0];
        const float4* p = (const float4*)g_Tpart;
#pragma unroll
        for (int u = 0; u < 4; ++u) {
            int i = b * 1024 + u * 256 + t;
            float4 s = p[i];
#pragma unroll
            for (int k = 1; k < KST; k++) {
                float4 v = p[k * (NB * DD / 4) + i];
                s.x += v.x; s.y += v.y; s.z += v.z; s.w += v.w;
            }
            float4 c4 = ((const float4*)g_c)[i & (DD / 4 - 1)];
            s.x = sc * (s.x + c4.x); s.y = sc * (s.y + c4.y);
            s.z = sc * (s.z + c4.z); s.w = sc * (s.w + c4.w);
            ((float4*)g_temp)[i] = s;
        }
    }
}

// ---------------------------------------------------------------------------
// out[l,b,d] = momery[l,b,d] + temp[b,d]
// momery should be L2-resident from the prefetch; stream stores for out.
// ---------------------------------------------------------------------------
#define BD4 (NB * DD / 4)   // 131072, power of two

__global__ __launch_bounds__(256) void k_add(const float4* __restrict__ mom,
                                             float4* __restrict__ out, int n4) {
    const float4* tp = (const float4*)g_temp;
    int stride = gridDim.x * blockDim.x;
    for (int i = blockIdx.x * blockDim.x + threadIdx.x; i < n4; i += stride) {
        float4 m = mom[i];
        float4 tv = tp[i & (BD4 - 1)];
        m.x += tv.x; m.y += tv.y; m.z += tv.z; m.w += tv.w;
        __stcs(&out[i], m);
    }
}

// ---------------------------------------------------------------------------
// Launch. Inputs (metadata order):
// 0 momery, 1 hid, 2 text_polarity, 3 attribute_polarity, 4 w,
// 5 p_w1, 6 p_b1, 7 p_w2, 8 p_b2, 9 wq, 10 bq, 11 wk, 12 bk,
// 13 wv, 14 bv, 15 wo, 16 bo
// ---------------------------------------------------------------------------
extern "C" void kernel_launch(void* const* d_in, const int* in_sizes, int n_in,
                              void* d_out, int out_size) {
    const float* momery = (const float*)d_in[0];
    const float* hid    = (const float*)d_in[1];
    const float* w      = (const float*)d_in[4];
    const float* wv     = (const float*)d_in[13];
    const float* bv     = (const float*)d_in[14];
    const float* wo     = (const float*)d_in[15];
    const float* bo     = (const float*)d_in[16];
    float* out = (float*)d_out;

    cudaFuncSetAttribute(k_fused, cudaFuncAttributeMaxDynamicSharedMemorySize,
                         SMEM_BYTES);

    k_fused<<<NBLK + NPREF, 256, SMEM_BYTES>>>(wo, wv, hid, bv, bo, w,
                                               (const float4*)momery);

    k_add<<<6144, 256>>>((const float4*)momery, (float4*)out, N4ALL);
}

// round 7
// speedup vs baseline: 1.0985x; 1.0985x over previous
#include <cuda_runtime.h>
#include <cstdint>

#define DD      512
#define HK      2048
#define NB      1024
#define LSLOTS  50
#define KSW     16           // split-K for W gemm
#define KST     8            // split-K for temp gemm
#define NBLK    256          // compute blocks participating in grid barrier
#define N4ALL   (LSLOTS * NB * DD / 4)   // 6,553,600 float4

// Scratch (static device globals — no allocation)
__device__ float g_Wpart[KSW * DD * DD];     // split-K partials of Wt[j,a] (16 MB)
__device__ float g_W[DD * DD];               // Wt[j][a] = (wv@wo)[a][j]
__device__ float g_c[DD];                    // bv@wo + bo
__device__ float g_Tpart[KST * NB * DD];     // split-K partials (16 MB)
__device__ float g_temp[NB * DD];            // 3w*(hid@W + c)

// grid barrier state (generation persists across replays; monotone)
__device__ int g_bar_count = 0;
__device__ volatile int g_bar_gen = 0;

__device__ __forceinline__ void grid_bar() {
    __syncthreads();
    if (threadIdx.x == 0) {
        __threadfence();
        int gen = g_bar_gen;
        if (atomicAdd(&g_bar_count, 1) == NBLK - 1) {
            g_bar_count = 0;
            __threadfence();
            g_bar_gen = gen + 1;
        } else {
            while (g_bar_gen == gen) { }
        }
        __threadfence();
    }
    __syncthreads();
}

// ---------------------------------------------------------------------------
// helpers
// ---------------------------------------------------------------------------
__device__ __forceinline__ uint32_t f2tf(float x) {
    uint32_t r; asm("cvt.rna.tf32.f32 %0, %1;" : "=r"(r) : "f"(x)); return r;
}
__device__ __forceinline__ void mma8(float* d, const uint32_t* a, const uint32_t* b) {
    asm volatile(
        "mma.sync.aligned.m16n8k8.row.col.f32.tf32.tf32.f32 "
        "{%0,%1,%2,%3}, {%4,%5,%6,%7}, {%8,%9}, {%0,%1,%2,%3};"
        : "+f"(d[0]), "+f"(d[1]), "+f"(d[2]), "+f"(d[3])
        : "r"(a[0]), "r"(a[1]), "r"(a[2]), "r"(a[3]), "r"(b[0]), "r"(b[1]));
}

// ---------------------------------------------------------------------------
// TF32 mma.sync GEMM device fn: C[z][m,n] = sum_{k in chunk z} A[m,k]*B[n,k]
//   ATR=false: A row-major [m][LDA] K-contig; ATR=true: A is [k][LDA] m-contig.
// Tile 128x128, Kc=32 per stage, double-buffered smem, 256 threads / 8 warps.
// ---------------------------------------------------------------------------
#define ASZ    4608          // 128*36 words (ATR uses 32*132=4224 of it)
#define BSZ    4608
#define STAGE  (ASZ + BSZ)
#define SMEM_WORDS (2 * STAGE)
#define SMEM_BYTES (SMEM_WORDS * 4)

template<bool ATR, int LDA, int LDB, int MTOT, int NTOT, int KCHUNK>
__device__ __forceinline__ void gemm_dev(const float* __restrict__ Ag,
                                         const float* __restrict__ Bg,
                                         float* __restrict__ C,
                                         uint32_t* smem,
                                         int bx, int by, int bz) {
    const int t = threadIdx.x;
    const int nBase = bx * 128;
    const int mBase = by * 128;
    const int kb    = bz * KCHUNK;

    const bool isA = (t < 128);
    const int tt = t & 127;
    const int rr = tt >> 3;
    const int fc = tt & 7;
    const int jq = tt & 31;
    const int kr = tt >> 5;

    constexpr int NS = KCHUNK / 32;
    float4 rg[8];

#define LDG(s)                                                                  \
    {                                                                           \
        if (isA) {                                                              \
            if (ATR) {                                                          \
                _Pragma("unroll")                                               \
                for (int i = 0; i < 8; ++i)                                     \
                    rg[i] = *(const float4*)&Ag[(size_t)(kb + (s)*32 + kr + 4*i) * LDA \
                                                + mBase + jq * 4];              \
            } else {                                                            \
                _Pragma("unroll")                                               \
                for (int i = 0; i < 8; ++i)                                     \
                    rg[i] = *(const float4*)&Ag[(size_t)(mBase + rr + 16*i) * LDA \
                                                + kb + (s)*32 + fc * 4];        \
            }                                                                   \
        } else {                                                                \
            _Pragma("unroll")                                                   \
            for (int i = 0; i < 8; ++i)                                         \
                rg[i] = *(const float4*)&Bg[(size_t)(nBase + rr + 16*i) * LDB   \
                                            + kb + (s)*32 + fc * 4];            \
        }                                                                       \
    }

    const int w = t >> 5, lane = t & 31;
    const int moff = (w & 3) * 32;
    const int noff = (w >> 2) * 64;
    const int g = lane >> 2, q = lane & 3;

    float acc[2][8][4];
#pragma unroll
    for (int mt = 0; mt < 2; mt++)
#pragma unroll
        for (int nt = 0; nt < 8; nt++)
#pragma unroll
            for (int r = 0; r < 4; r++) acc[mt][nt][r] = 0.0f;

    LDG(0);

    for (int s = 0; s < NS; ++s) {
        const int buf = s & 1;
        uint32_t* dst = smem + buf * STAGE + (isA ? 0 : ASZ);
        if (isA && ATR) {
#pragma unroll
            for (int i = 0; i < 8; ++i) {
                uint32_t* p = dst + (kr + 4 * i) * 132 + jq * 4;
                p[0] = f2tf(rg[i].x); p[1] = f2tf(rg[i].y);
                p[2] = f2tf(rg[i].z); p[3] = f2tf(rg[i].w);
            }
        } else {
#pragma unroll
            for (int i = 0; i < 8; ++i) {
                uint32_t* p = dst + (rr + 16 * i) * 36 + fc * 4;
                p[0] = f2tf(rg[i].x); p[1] = f2tf(rg[i].y);
                p[2] = f2tf(rg[i].z); p[3] = f2tf(rg[i].w);
            }
        }
        __syncthreads();
        if (s + 1 < NS) LDG(s + 1);

        const uint32_t* As = smem + buf * STAGE;
        const uint32_t* Bs = As + ASZ;
#pragma unroll
        for (int k0 = 0; k0 < 32; k0 += 8) {
            uint32_t af[2][4];
#pragma unroll
            for (int mt = 0; mt < 2; mt++) {
                const int m0 = moff + mt * 16 + g;
                if (ATR) {
                    af[mt][0] = As[(k0 + q) * 132 + m0];
                    af[mt][1] = As[(k0 + q) * 132 + m0 + 8];
                    af[mt][2] = As[(k0 + q + 4) * 132 + m0];
                    af[mt][3] = As[(k0 + q + 4) * 132 + m0 + 8];
                } else {
                    af[mt][0] = As[m0 * 36 + k0 + q];
                    af[mt][1] = As[(m0 + 8) * 36 + k0 + q];
                    af[mt][2] = As[m0 * 36 + k0 + q + 4];
                    af[mt][3] = As[(m0 + 8) * 36 + k0 + q + 4];
                }
            }
            uint32_t bf[8][2];
#pragma unroll
            for (int nt = 0; nt < 8; nt++) {
                const int n0 = noff + nt * 8 + g;
                bf[nt][0] = Bs[n0 * 36 + k0 + q];
                bf[nt][1] = Bs[n0 * 36 + k0 + q + 4];
            }
#pragma unroll
            for (int mt = 0; mt < 2; mt++)
#pragma unroll
                for (int nt = 0; nt < 8; nt++)
                    mma8(acc[mt][nt], af[mt], bf[nt]);
        }
        __syncthreads();
    }
#undef LDG

    float* cz = C + (size_t)bz * MTOT * NTOT;
#pragma unroll
    for (int mt = 0; mt < 2; mt++) {
        const int r0 = mBase + moff + mt * 16 + g;
#pragma unroll
        for (int nt = 0; nt < 8; nt++) {
            const int c0 = nBase + noff + nt * 8 + q * 2;
            float2 v0 = make_float2(acc[mt][nt][0], acc[mt][nt][1]);
            float2 v1 = make_float2(acc[mt][nt][2], acc[mt][nt][3]);
            *(float2*)&cz[(size_t)r0 * NTOT + c0] = v0;
            *(float2*)&cz[(size_t)(r0 + 8) * NTOT + c0] = v1;
        }
    }
}

// ---------------------------------------------------------------------------
// Fused persistent kernel, 256 blocks, 2 blocks/SM.
// P0 gemm_w (16 tiles x 16 k-slices) | P1 reduce_w + bias_c |
// P2 gemm_temp (32 tiles x 8 k-slices) | P3 reduce_temp.
// ---------------------------------------------------------------------------
__global__ __launch_bounds__(256, 2) void k_fused(const float* __restrict__ wo,
                                                  const float* __restrict__ wv,
                                                  const float* __restrict__ hid,
                                                  const float* __restrict__ bv,
                                                  const float* __restrict__ bo,
                                                  const float* __restrict__ wsc) {
    extern __shared__ uint32_t smem[];
    __shared__ float sred[8];
    const int b = blockIdx.x;
    const int t = threadIdx.x;

    // ---- P0: Wt partials  Wt[j,a] = sum_k wo[k,j] * wv[a,k]
    // tile = b & 15 -> bx = tile&3, by = tile>>2 ; bz = b >> 4 (0..15)
    gemm_dev<true, DD, HK, DD, DD, HK / KSW>(wo, wv, g_Wpart, smem,
                                             b & 3, (b >> 2) & 3, b >> 4);
    grid_bar();

    // ---- P1a: reduce W partials (65536 float4 over 256 blocks => 1/thread)
    {
        const float4* p = (const float4*)g_Wpart;
        int i = b * 256 + t;
        float4 s = p[i];
#pragma unroll
        for (int k = 1; k < KSW; k++) {
            float4 v = p[k * (DD * DD / 4) + i];
            s.x += v.x; s.y += v.y; s.z += v.z; s.w += v.w;
        }
        ((float4*)g_W)[i] = s;
    }
    // ---- P1b: bias c[j] = sum_k bv[k]*wo[k,j] + bo[j]  (2 j's per block)
    {
        const int jloc = t >> 7;               // 0..1
        const int j = b * 2 + jloc;
        const int tk = t & 127;
        float acc = 0.0f;
        const int k0 = tk * 16;
        for (int k = k0; k < k0 + 16; k++)
            acc += bv[k] * wo[(size_t)k * DD + j];
#pragma unroll
        for (int off = 16; off > 0; off >>= 1)
            acc += __shfl_down_sync(0xFFFFFFFFu, acc, off);
        if ((t & 31) == 0) sred[t >> 5] = acc;
        __syncthreads();
        if (t < 2)
            g_c[b * 2 + t] = sred[4 * t] + sred[4 * t + 1] + sred[4 * t + 2]
                           + sred[4 * t + 3] + bo[b * 2 + t];
    }
    grid_bar();

    // ---- P2: temp partials  Tpart[z][b,j] = sum_a hid[b,a]*Wt[j,a]
    // tile = b & 31 -> bx = tile&3, by = tile>>2 ; bz = b >> 5 (0..7)
    gemm_dev<false, DD, DD, NB, DD, DD / KST>(hid, g_W, g_Tpart, smem,
                                              b & 3, (b >> 2) & 7, b >> 5);
    grid_bar();

    // ---- P3: temp = 3w * (sum partials + c)   (131072 float4 => 2/thread)
    {
        const float sc = 3.0f * wsc[0];
        const float4* p = (const float4*)g_Tpart;
#pragma unroll
        for (int u = 0; u < 2; ++u) {
            int i = b * 512 + u * 256 + t;
            float4 s = p[i];
#pragma unroll
            for (int k = 1; k < KST; k++) {
                float4 v = p[k * (NB * DD / 4) + i];
                s.x += v.x; s.y += v.y; s.z += v.z; s.w += v.w;
            }
            float4 c4 = ((const float4*)g_c)[i & (DD / 4 - 1)];
            s.x = sc * (s.x + c4.x); s.y = sc * (s.y + c4.y);
            s.z = sc * (s.z + c4.z); s.w = sc * (s.w + c4.w);
            ((float4*)g_temp)[i] = s;
        }
    }
}

// ---------------------------------------------------------------------------
// out[l,b,d] = momery[l,b,d] + temp[b,d]
// ---------------------------------------------------------------------------
#define BD4 (NB * DD / 4)   // 131072, power of two

__global__ __launch_bounds__(256) void k_add(const float4* __restrict__ mom,
                                             float4* __restrict__ out, int n4) {
    const float4* tp = (const float4*)g_temp;
    int stride = gridDim.x * blockDim.x;
    for (int i = blockIdx.x * blockDim.x + threadIdx.x; i < n4; i += stride) {
        float4 m = mom[i];
        float4 tv = tp[i & (BD4 - 1)];
        m.x += tv.x; m.y += tv.y; m.z += tv.z; m.w += tv.w;
        __stcs(&out[i], m);
    }
}

// ---------------------------------------------------------------------------
// Launch. Inputs (metadata order):
// 0 momery, 1 hid, 2 text_polarity, 3 attribute_polarity, 4 w,
// 5 p_w1, 6 p_b1, 7 p_w2, 8 p_b2, 9 wq, 10 bq, 11 wk, 12 bk,
// 13 wv, 14 bv, 15 wo, 16 bo
// ---------------------------------------------------------------------------
extern "C" void kernel_launch(void* const* d_in, const int* in_sizes, int n_in,
                              void* d_out, int out_size) {
    const float* momery = (const float*)d_in[0];
    const float* hid    = (const float*)d_in[1];
    const float* w      = (const float*)d_in[4];
    const float* wv     = (const float*)d_in[13];
    const float* bv     = (const float*)d_in[14];
    const float* wo     = (const float*)d_in[15];
    const float* bo     = (const float*)d_in[16];
    float* out = (float*)d_out;

    cudaFuncSetAttribute(k_fused, cudaFuncAttributeMaxDynamicSharedMemorySize,
                         SMEM_BYTES);

    k_fused<<<NBLK, 256, SMEM_BYTES>>>(wo, wv, hid, bv, bo, w);

    k_add<<<6144, 256>>>((const float4*)momery, (float4*)out, N4ALL);
}